// round 7
// baseline (speedup 1.0000x reference)
#include <cuda_runtime.h>
#include <cuda_fp16.h>
#include <cuda_bf16.h>
#include <math.h>
#include <stdint.h>

// Problem constants
#define BATCH 32
#define SEQ   2048
#define HID   1024
#define KDIM  3072          // 3*HID
#define MROWS (BATCH*SEQ)   // 65536

// Scratch (device globals: allocation-free rule)
__device__ float  g_w[BATCH * SEQ];            // softmax weights
__device__ float  g_pp[8][BATCH * KDIM];       // pooled-trg partials (8 L-splits)
__device__ float  g_np[8][MROWS];              // per-n-tile rowsq partials
__device__ __half g_trgh[(size_t)MROWS * KDIM];// fp16 trg (403 MB)
__device__ __half g_wh[(size_t)HID * KDIM];    // fp16 W   (6 MB)

// ---------------------------------------------------------------------------
// helpers
// ---------------------------------------------------------------------------
__device__ __forceinline__ uint32_t smem_u32(const void* p) {
    uint32_t a;
    asm("{ .reg .u64 t; cvta.to.shared.u64 t, %1; cvt.u32.u64 %0, t; }"
        : "=r"(a) : "l"(p));
    return a;
}

__device__ __forceinline__ void cp16(uint32_t saddr, const void* gaddr) {
    asm volatile("cp.async.cg.shared.global [%0], [%1], 16;"
                 :: "r"(saddr), "l"(gaddr) : "memory");
}

__device__ __forceinline__ void ldsm_x4(uint32_t& r0, uint32_t& r1,
                                        uint32_t& r2, uint32_t& r3, uint32_t addr) {
    asm volatile("ldmatrix.sync.aligned.m8n8.x4.shared.b16 {%0,%1,%2,%3}, [%4];"
                 : "=r"(r0), "=r"(r1), "=r"(r2), "=r"(r3) : "r"(addr));
}

__device__ __forceinline__ void mma_f16(float& d0, float& d1, float& d2, float& d3,
                                        uint32_t a0, uint32_t a1, uint32_t a2, uint32_t a3,
                                        uint32_t b0, uint32_t b1) {
    asm volatile(
        "mma.sync.aligned.m16n8k16.row.col.f32.f16.f16.f32 "
        "{%0,%1,%2,%3}, {%4,%5,%6,%7}, {%8,%9}, {%0,%1,%2,%3};"
        : "+f"(d0), "+f"(d1), "+f"(d2), "+f"(d3)
        : "r"(a0), "r"(a1), "r"(a2), "r"(a3), "r"(b0), "r"(b1));
}

// ---------------------------------------------------------------------------
// Kernel 0: fp32 -> fp16 conversion, 8 elements/thread
// ---------------------------------------------------------------------------
__global__ __launch_bounds__(256)
void k_cvt8(const float* __restrict__ in, __half* __restrict__ out)
{
    const size_t i = ((size_t)blockIdx.x * 256 + threadIdx.x) * 8;
    float4 v0 = *(const float4*)(in + i);
    float4 v1 = *(const float4*)(in + i + 4);
    __half2 h0 = __floats2half2_rn(v0.x, v0.y);
    __half2 h1 = __floats2half2_rn(v0.z, v0.w);
    __half2 h2 = __floats2half2_rn(v1.x, v1.y);
    __half2 h3 = __floats2half2_rn(v1.z, v1.w);
    uint4 u;
    u.x = *(uint32_t*)&h0; u.y = *(uint32_t*)&h1;
    u.z = *(uint32_t*)&h2; u.w = *(uint32_t*)&h3;
    *(uint4*)(out + i) = u;
}

// ---------------------------------------------------------------------------
// Kernel 1: partial rowsq for one 128x128 output tile, full K.
// fp16 mma.sync m16n8k16 + ldmatrix.x4, 3-stage cp.async ring,
// ONE __syncthreads per stage. XOR-swizzled smem.
// grid (8 n-tiles, 512 m-blocks); 256 threads, warp grid 4(M) x 2(N).
// ---------------------------------------------------------------------------
#define BKH    64                              // k-halves per stage
#define STG_B  (2 * 128 * 128)                 // bytes per stage (A+B, 32 KB)
#define SMEM_NORM (3 * STG_B)                  // 96 KB
#define NSTG   (KDIM / BKH)                    // 48

__global__ __launch_bounds__(256, 2)
void k_norm_h(const float* __restrict__ bias)
{
    extern __shared__ __align__(128) char smem[];
    const uint32_t sb = smem_u32(smem);
    // stage st: A at sb + st*STG_B, B at sb + st*STG_B + 16KB
    uint32_t sA[3], sB[3];
    #pragma unroll
    for (int st = 0; st < 3; ++st) {
        sA[st] = sb + st * STG_B;
        sB[st] = sb + st * STG_B + 128 * 128;
    }

    __shared__ float rowsq_s[128][2];

    const int tid  = threadIdx.x;
    const int lane = tid & 31;
    const int w    = tid >> 5;
    const int wy   = w >> 1;                  // 0..3  (M)
    const int wx   = w & 1;                   // 0..1  (N)
    const int g    = lane >> 2;               // 0..7
    const int tig  = lane & 3;                // 0..3
    const int WM   = wy * 32;
    const int WN   = wx * 64;
    const int    nx = blockIdx.x;             // n-tile 0..7
    const int    n0 = nx * 128;
    const size_t m0 = (size_t)blockIdx.y * 128;

    // ---- cp.async indexing: 1024 16B-chunks per tile, 4 per thread ----
    const int lrow[4] = { (tid + 0*256) >> 3, (tid + 1*256) >> 3,
                          (tid + 2*256) >> 3, (tid + 3*256) >> 3 };
    const int lc     = tid & 7;
    const int lcol8  = lc * 8;
    int soff[4];
    #pragma unroll
    for (int i = 0; i < 4; ++i)
        soff[i] = lrow[i] * 128 + ((lc ^ (lrow[i] & 7)) << 4);

    const __half* gA = g_trgh + m0 * (size_t)KDIM;
    const __half* gB = g_wh + (size_t)n0 * KDIM;

    // ---- ldmatrix per-lane row bases ----
    const int sub  = ((lane >> 3) & 1) * 8 + (lane & 7);
    const int hi   = (lane >> 4) & 1;
    const int mod7 = lane & 7;
    int aoff[2], boff[4];
    #pragma unroll
    for (int mt = 0; mt < 2; ++mt) aoff[mt] = (WM + mt*16 + sub) * 128;
    #pragma unroll
    for (int j = 0; j < 4; ++j)    boff[j]  = (WN + j*16  + sub) * 128;

    float acc[2][8][4];
    #pragma unroll
    for (int mt = 0; mt < 2; ++mt)
        #pragma unroll
        for (int nt = 0; nt < 8; ++nt)
            #pragma unroll
            for (int c = 0; c < 4; ++c) acc[mt][nt][c] = 0.f;

    // prologue: stages 0 and 1
    #pragma unroll
    for (int st = 0; st < 2; ++st) {
        const int kk = st * BKH;
        #pragma unroll
        for (int i = 0; i < 4; ++i) {
            cp16(sA[st] + soff[i], gA + (size_t)lrow[i] * KDIM + kk + lcol8);
            cp16(sB[st] + soff[i], gB + (size_t)lrow[i] * KDIM + kk + lcol8);
        }
        asm volatile("cp.async.commit_group;" ::: "memory");
    }

    int slot = 0;            // buffer slot of stage s
    int nslot = 2;           // slot receiving stage s+2
    for (int s = 0; s < NSTG; ++s) {
        // stage s landed?
        if (s < NSTG - 1) asm volatile("cp.async.wait_group 1;" ::: "memory");
        else              asm volatile("cp.async.wait_group 0;" ::: "memory");
        __syncthreads();     // also: all warps done with stage s-1 (slot nslot)

        // issue stage s+2 into retired slot, under compute of stage s
        if (s + 2 < NSTG) {
            const int k2 = (s + 2) * BKH;
            #pragma unroll
            for (int i = 0; i < 4; ++i) {
                cp16(sA[nslot] + soff[i], gA + (size_t)lrow[i] * KDIM + k2 + lcol8);
                cp16(sB[nslot] + soff[i], gB + (size_t)lrow[i] * KDIM + k2 + lcol8);
            }
            asm volatile("cp.async.commit_group;" ::: "memory");
        }

        const uint32_t bA = sA[slot];
        const uint32_t bB = sB[slot];
        #pragma unroll
        for (int ks = 0; ks < BKH / 16; ++ks) {
            const uint32_t sw = (uint32_t)(((ks*2 + hi) ^ mod7) << 4);
            uint32_t af[2][4], bf[8][2];
            #pragma unroll
            for (int mt = 0; mt < 2; ++mt)
                ldsm_x4(af[mt][0], af[mt][1], af[mt][2], af[mt][3],
                        bA + aoff[mt] + sw);
            #pragma unroll
            for (int j = 0; j < 4; ++j)
                ldsm_x4(bf[2*j][0], bf[2*j+1][0], bf[2*j][1], bf[2*j+1][1],
                        bB + boff[j] + sw);
            #pragma unroll
            for (int mt = 0; mt < 2; ++mt)
                #pragma unroll
                for (int nt = 0; nt < 8; ++nt)
                    mma_f16(acc[mt][nt][0], acc[mt][nt][1],
                            acc[mt][nt][2], acc[mt][nt][3],
                            af[mt][0], af[mt][1], af[mt][2], af[mt][3],
                            bf[nt][0], bf[nt][1]);
        }

        slot  = (slot  == 2) ? 0 : slot + 1;
        nslot = (nslot == 2) ? 0 : nslot + 1;
    }

    // epilogue: +bias, square-accumulate per row (partial over this n-tile)
    float rowsq[4] = {0.f, 0.f, 0.f, 0.f};
    #pragma unroll
    for (int nt = 0; nt < 8; ++nt) {
        const int cb = n0 + WN + nt*8 + 2*tig;
        const float b0 = __ldg(bias + cb);
        const float b1 = __ldg(bias + cb + 1);
        #pragma unroll
        for (int mt = 0; mt < 2; ++mt) {
            float v0 = acc[mt][nt][0] + b0;
            float v1 = acc[mt][nt][1] + b1;
            float v2 = acc[mt][nt][2] + b0;
            float v3 = acc[mt][nt][3] + b1;
            rowsq[mt*2+0] = fmaf(v0, v0, rowsq[mt*2+0]);
            rowsq[mt*2+0] = fmaf(v1, v1, rowsq[mt*2+0]);
            rowsq[mt*2+1] = fmaf(v2, v2, rowsq[mt*2+1]);
            rowsq[mt*2+1] = fmaf(v3, v3, rowsq[mt*2+1]);
        }
    }
    #pragma unroll
    for (int i = 0; i < 4; ++i) {
        rowsq[i] += __shfl_xor_sync(0xffffffffu, rowsq[i], 1);
        rowsq[i] += __shfl_xor_sync(0xffffffffu, rowsq[i], 2);
    }
    if (tig == 0) {
        #pragma unroll
        for (int mt = 0; mt < 2; ++mt)
            #pragma unroll
            for (int i = 0; i < 2; ++i)
                rowsq_s[WM + mt*16 + i*8 + g][wx] = rowsq[mt*2 + i];
    }
    __syncthreads();
    if (tid < 128)
        g_np[nx][m0 + tid] = rowsq_s[tid][0] + rowsq_s[tid][1];
}

// ---------------------------------------------------------------------------
// Kernel 2: combine rowsq partials -> norm1, then softmax over L -> g_w
// ---------------------------------------------------------------------------
__global__ void k_softmax(float* __restrict__ norm1)
{
    const int b = blockIdx.x;
    const int tid = threadIdx.x;
    __shared__ float red[256];

    for (int l = tid; l < SEQ; l += 256) {
        const int m = b * SEQ + l;
        float s = 0.f;
        #pragma unroll
        for (int j = 0; j < 8; ++j) s += g_np[j][m];
        norm1[m] = sqrtf(s);
    }
    __syncthreads();

    const float* x = norm1 + b * SEQ;
    float m = -1e30f;
    for (int l = tid; l < SEQ; l += 256) m = fmaxf(m, x[l]);
    red[tid] = m; __syncthreads();
    for (int s = 128; s > 0; s >>= 1) {
        if (tid < s) red[tid] = fmaxf(red[tid], red[tid + s]);
        __syncthreads();
    }
    float bm = red[0];
    __syncthreads();

    float sum = 0.0f;
    for (int l = tid; l < SEQ; l += 256) {
        float e = __expf(x[l] - bm);
        g_w[b * SEQ + l] = e;
        sum += e;
    }
    red[tid] = sum; __syncthreads();
    for (int s = 128; s > 0; s >>= 1) {
        if (tid < s) red[tid] += red[tid + s];
        __syncthreads();
    }
    float inv = 1.0f / red[0];
    for (int l = tid; l < SEQ; l += 256) g_w[b * SEQ + l] *= inv;
}

// ---------------------------------------------------------------------------
// Kernel 3: pooled partials from fp16 trg: g_pp[ls][b,k] = sum w[b,l]*trg[b,l,k]
// ---------------------------------------------------------------------------
__global__ void k_pool(void)
{
    const int kc = blockIdx.x;            // 0..2
    const int ls = blockIdx.y;            // 0..7
    const int b  = blockIdx.z;            // 0..31
    const int tid = threadIdx.x;
    const int k0 = kc * 1024 + tid * 4;

    const __half* base = g_trgh + (size_t)b * SEQ * KDIM;
    float4 acc = make_float4(0.f, 0.f, 0.f, 0.f);

    const int l0 = ls * 256;
    #pragma unroll 4
    for (int l = l0; l < l0 + 256; ++l) {
        float wl = g_w[b * SEQ + l];
        uint2 raw = *(const uint2*)(base + (size_t)l * KDIM + k0);
        float2 f0 = __half22float2(*(__half2*)&raw.x);
        float2 f1 = __half22float2(*(__half2*)&raw.y);
        acc.x = fmaf(wl, f0.x, acc.x);
        acc.y = fmaf(wl, f0.y, acc.y);
        acc.z = fmaf(wl, f1.x, acc.z);
        acc.w = fmaf(wl, f1.y, acc.w);
    }
    *(float4*)(&g_pp[ls][b * KDIM + k0]) = acc;
}

// ---------------------------------------------------------------------------
// Kernel 4: summ[b,h] = p[b,:] . W[h,:] + bias[h]   (fp32 W for accuracy)
// ---------------------------------------------------------------------------
__global__ void k_out(const float* __restrict__ W, const float* __restrict__ bias,
                      float* __restrict__ summ)
{
    const int b = blockIdx.y;
    const int tid = threadIdx.x;
    const int lane = tid & 31;
    const int wid = tid >> 5;

    __shared__ float ps[KDIM];
    for (int k = tid; k < KDIM; k += 256) {
        float s = 0.0f;
        #pragma unroll
        for (int l = 0; l < 8; ++l) s += g_pp[l][b * KDIM + k];
        ps[k] = s;
    }
    __syncthreads();

    const int h = blockIdx.x * 8 + wid;
    const float* wr = W + (size_t)h * KDIM;
    float s = 0.0f;
    for (int k = lane * 4; k < KDIM; k += 128) {
        float4 v = *(const float4*)(wr + k);
        float4 u = *(const float4*)(ps + k);
        s = fmaf(v.x, u.x, s); s = fmaf(v.y, u.y, s);
        s = fmaf(v.z, u.z, s); s = fmaf(v.w, u.w, s);
    }
    #pragma unroll
    for (int o = 16; o > 0; o >>= 1) s += __shfl_xor_sync(0xffffffffu, s, o);
    if (lane == 0) summ[b * HID + h] = s + bias[h];
}

// ---------------------------------------------------------------------------
extern "C" void kernel_launch(void* const* d_in, const int* in_sizes, int n_in,
                              void* d_out, int out_size)
{
    const float* trg  = (const float*)d_in[0];
    // d_in[1] = src (unused, n_layers == 0)
    const float* W    = (const float*)d_in[2];
    const float* bias = (const float*)d_in[3];

    float* out   = (float*)d_out;
    float* summ  = out;                   // [32, 1024]
    float* norm1 = out + BATCH * HID;     // [32, 2048]

    __half* trgh; cudaGetSymbolAddress((void**)&trgh, g_trgh);
    __half* wh;   cudaGetSymbolAddress((void**)&wh,   g_wh);

    cudaFuncSetAttribute(k_norm_h, cudaFuncAttributeMaxDynamicSharedMemorySize, SMEM_NORM);

    k_cvt8<<<(HID * KDIM) / (256 * 8), 256>>>(W, wh);
    k_cvt8<<<((size_t)MROWS * KDIM) / (256 * 8), 256>>>(trg, trgh);
    k_norm_h<<<dim3(8, MROWS / 128), 256, SMEM_NORM>>>(bias);
    k_softmax<<<BATCH, 256>>>(norm1);
    k_pool<<<dim3(3, 8, BATCH), 256>>>();
    k_out<<<dim3(HID / 8, BATCH), 256>>>(W, bias, summ);
}